// round 7
// baseline (speedup 1.0000x reference)
#include <cuda_runtime.h>
#include <math.h>
#include <stdint.h>

#define BB   2
#define SS   2048
#define DD   2048
#define HH   16
#define HD   128
#define DFF  8192
#define MROW 4096
#define QS   6144
#define EPSV 1e-5f

// ---------------- scratch ----------------
static __device__ float g_xn  [(size_t)MROW*DD];
static __device__ float g_qkv [(size_t)MROW*QS];
static __device__ float g_ctx [(size_t)MROW*DD];
static __device__ float g_h   [(size_t)MROW*DD];
static __device__ float g_ff  [(size_t)MROW*DFF];
static __device__ float g_wqkv[(size_t)DD*QS];
static __device__ float g_wo  [(size_t)DD*DD];
static __device__ float g_w1  [(size_t)DD*DFF];
static __device__ float g_w2  [(size_t)DFF*DD];

// ---------------- helpers ----------------
__device__ __forceinline__ uint32_t smem_u32(const void* p) {
    uint32_t a;
    asm("{ .reg .u64 t; cvta.to.shared.u64 t, %1; cvt.u32.u64 %0, t; }" : "=r"(a) : "l"(p));
    return a;
}
__device__ __forceinline__ void cp_async16(uint32_t s, const void* g) {
    asm volatile("cp.async.cg.shared.global [%0], [%1], 16;" :: "r"(s), "l"(g));
}
__device__ __forceinline__ void cp_commit() {
    asm volatile("cp.async.commit_group;" ::: "memory");
}
__device__ __forceinline__ void cp_wait1() {
    asm volatile("cp.async.wait_group 1;" ::: "memory");
}
__device__ __forceinline__ float rtf32(float x) {
    uint32_t r;
    asm("cvt.rna.tf32.f32 %0, %1;" : "=r"(r) : "f"(x));
    return __uint_as_float(r);
}
__device__ __forceinline__ void mma_tf32(float* c, const uint32_t* a, const uint32_t* b) {
    asm volatile("mma.sync.aligned.m16n8k8.row.col.f32.tf32.tf32.f32 "
        "{%0,%1,%2,%3}, {%4,%5,%6,%7}, {%8,%9}, {%0,%1,%2,%3};"
        : "+f"(c[0]), "+f"(c[1]), "+f"(c[2]), "+f"(c[3])
        : "r"(a[0]), "r"(a[1]), "r"(a[2]), "r"(a[3]), "r"(b[0]), "r"(b[1]));
}
__device__ __forceinline__ float gelu_f(float x) {
    float x3 = x*x*x;
    return 0.5f * x * (1.0f + tanhf(0.79788456080286536f * (x + 0.044715f*x3)));
}

// ---------------- TF32 pre-round ----------------
__global__ __launch_bounds__(256)
void round_tf32_kernel(const float* __restrict__ src, float* __restrict__ dst, int n4) {
    int i = blockIdx.x*256 + threadIdx.x;
    if (i < n4) {
        float4 v = ((const float4*)src)[i];
        v.x = rtf32(v.x); v.y = rtf32(v.y); v.z = rtf32(v.z); v.w = rtf32(v.w);
        ((float4*)dst)[i] = v;
    }
}
// round Wq/Wk/Wv [2048,2048] into packed wqkv [2048,6144] at column offset
__global__ __launch_bounds__(256)
void round_tf32_pack(const float* __restrict__ src, float* __restrict__ dst,
                     int n4, int colOff) {
    int i = blockIdx.x*256 + threadIdx.x;
    if (i < n4) {
        float4 v = ((const float4*)src)[i];
        v.x = rtf32(v.x); v.y = rtf32(v.y); v.z = rtf32(v.z); v.w = rtf32(v.w);
        int r = i >> 9;            // 512 float4 per 2048-row
        int c = i & 511;
        *(float4*)(dst + (size_t)r*QS + colOff + c*4) = v;
    }
}

// ---------------- LayerNorm (tf32-rounded output) ----------------
__global__ __launch_bounds__(256)
void ln_kernel(const float* __restrict__ x, const float* __restrict__ sc,
               const float* __restrict__ sh, float* __restrict__ out) {
    int row = blockIdx.x;
    const float* xr = x + (size_t)row * DD;
    float v[8];
    float s = 0.f, sq = 0.f;
#pragma unroll
    for (int i = 0; i < 8; i++) {
        v[i] = xr[threadIdx.x + i*256];
        s += v[i]; sq += v[i]*v[i];
    }
    __shared__ float rs[8], rq[8];
    __shared__ float s_mean, s_rstd;
#pragma unroll
    for (int o = 16; o > 0; o >>= 1) {
        s  += __shfl_down_sync(0xFFFFFFFFu, s,  o);
        sq += __shfl_down_sync(0xFFFFFFFFu, sq, o);
    }
    int w = threadIdx.x >> 5;
    if ((threadIdx.x & 31) == 0) { rs[w] = s; rq[w] = sq; }
    __syncthreads();
    if (threadIdx.x == 0) {
        float ts = 0.f, tq = 0.f;
#pragma unroll
        for (int i = 0; i < 8; i++) { ts += rs[i]; tq += rq[i]; }
        float mean = ts * (1.0f/DD);
        s_mean = mean;
        s_rstd = rsqrtf(tq * (1.0f/DD) - mean*mean + EPSV);
    }
    __syncthreads();
    float mean = s_mean, rstd = s_rstd;
    float* orow = out + (size_t)row * DD;
#pragma unroll
    for (int i = 0; i < 8; i++) {
        int d = threadIdx.x + i*256;
        orow[d] = rtf32(sc[d]*(v[i]-mean)*rstd + sh[d]);
    }
}

// ---------------- TF32 tensor-core GEMM (CTA 128x256, warp 64x64) ----------------
#define KSTEP   32
#define NSTG    3
#define A_ROWF  36
#define B_ROWF  264
#define A_BYTES (128*A_ROWF*4)           // 18432
#define B_BYTES (KSTEP*B_ROWF*4)         // 33792
#define STG_B   (A_BYTES + B_BYTES)      // 52224
#define G_SMEM  (NSTG*STG_B)             // 156672

template<int EPI>
__global__ __launch_bounds__(256, 1)
void mma_gemm(const float* __restrict__ A, const float* __restrict__ B,
              const float* __restrict__ bias, const float* __restrict__ R,
              float* __restrict__ C, int N, int K) {
    extern __shared__ char dsm[];
    const int tid = threadIdx.x;
    const int lane = tid & 31;
    const int wid = tid >> 5;
    const int warpM = wid & 1;           // 0..1 (64 rows each)
    const int warpN = wid >> 1;          // 0..3 (64 cols each)
    const int m0 = blockIdx.y * 128;
    const int n0 = blockIdx.x * 256;
    const uint32_t sb = smem_u32(dsm);

    float acc[4][8][4];
#pragma unroll
    for (int i = 0; i < 4; i++)
#pragma unroll
        for (int j = 0; j < 8; j++)
#pragma unroll
            for (int u = 0; u < 4; u++) acc[i][j][u] = 0.f;

    const int NT = K / KSTEP;

    auto load_stage = [&](int s, int kk) {
        uint32_t ab = sb + s*STG_B;
        uint32_t bbase = ab + A_BYTES;
#pragma unroll
        for (int i = 0; i < 4; i++) {
            int idx = i*256 + tid;
            int r = idx >> 3, c = idx & 7;
            cp_async16(ab + r*(A_ROWF*4) + c*16,
                       A + (size_t)(m0 + r)*K + kk + c*4);
        }
#pragma unroll
        for (int i = 0; i < 8; i++) {
            int idx = i*256 + tid;
            int r = idx >> 6, c = idx & 63;
            cp_async16(bbase + r*(B_ROWF*4) + c*16,
                       B + (size_t)(kk + r)*N + n0 + c*4);
        }
    };

    load_stage(0, 0); cp_commit();
    load_stage(1, KSTEP); cp_commit();

    const uint32_t* As_u = (const uint32_t*)dsm;
    const int arow = warpM*64 + (lane >> 2);
    const int acol = lane & 3;
    const int bq   = lane >> 2;
    const int brow = lane & 3;

    for (int t = 0; t < NT; t++) {
        cp_wait1();
        __syncthreads();
        if (t + 2 < NT) { load_stage((t+2)%NSTG, (t+2)*KSTEP); cp_commit(); }

        int s = t % NSTG;
        const uint32_t* Au = As_u + s*(STG_B/4);
        const uint32_t* Bu = Au + (A_BYTES/4);
#pragma unroll
        for (int k8 = 0; k8 < 4; k8++) {
            int kb = k8*8;
            uint32_t afr[4][4];
#pragma unroll
            for (int mt = 0; mt < 4; mt++) {
                int r = arow + mt*16;
                afr[mt][0] = Au[(r  )*A_ROWF + kb + acol    ];
                afr[mt][1] = Au[(r+8)*A_ROWF + kb + acol    ];
                afr[mt][2] = Au[(r  )*A_ROWF + kb + acol + 4];
                afr[mt][3] = Au[(r+8)*A_ROWF + kb + acol + 4];
            }
            uint32_t bfr[8][2];
#pragma unroll
            for (int nt = 0; nt < 8; nt++) {
                int cc = warpN*64 + nt*8 + bq;
                bfr[nt][0] = Bu[(kb + brow    )*B_ROWF + cc];
                bfr[nt][1] = Bu[(kb + brow + 4)*B_ROWF + cc];
            }
#pragma unroll
            for (int mt = 0; mt < 4; mt++)
#pragma unroll
                for (int nt = 0; nt < 8; nt++)
                    mma_tf32(acc[mt][nt], afr[mt], bfr[nt]);
        }
    }

#pragma unroll
    for (int mt = 0; mt < 4; mt++) {
#pragma unroll
        for (int half = 0; half < 2; half++) {
            int m = m0 + warpM*64 + mt*16 + (lane >> 2) + half*8;
#pragma unroll
            for (int nt = 0; nt < 8; nt++) {
                int n = n0 + warpN*64 + nt*8 + 2*(lane & 3);
                float v0 = acc[mt][nt][half*2 + 0];
                float v1 = acc[mt][nt][half*2 + 1];
                if (EPI == 1) {
                    const float2 bb = *(const float2*)(bias + n);
                    const float2 rr = *(const float2*)(R + (size_t)m*N + n);
                    v0 += bb.x + rr.x;
                    v1 += bb.y + rr.y;
                } else if (EPI == 2) {
                    const float2 bb = *(const float2*)(bias + n);
                    v0 = rtf32(gelu_f(v0 + bb.x));
                    v1 = rtf32(gelu_f(v1 + bb.y));
                }
                float2 o; o.x = v0; o.y = v1;
                *(float2*)(C + (size_t)m*N + n) = o;
            }
        }
    }
}

// ---------------- causal flash attention (TF32 tensor cores) ----------------
#define QROWF 132
#define VROWF 68
#define ATT_SMEM ((128*QROWF + 64*QROWF + 128*VROWF + 128*VROWF) * 4)

__global__ __launch_bounds__(256, 1)
void attn_mma(const float* __restrict__ Q, const float* __restrict__ Kg,
              const float* __restrict__ V, float* __restrict__ O, int ld) {
    extern __shared__ float sm[];
    float* Qs = sm;
    float* Ks = Qs + 128*QROWF;
    float* Vt = Ks + 64*QROWF;
    float* Ps = Vt + 128*VROWF;

    const int tid = threadIdx.x;
    const int lane = tid & 31;
    const int w = tid >> 5;
    const int r0 = lane >> 2;
    const int c0 = lane & 3;
    const int q0 = blockIdx.x * 128;
    const int b = blockIdx.y >> 4;
    const int h = blockIdx.y & 15;
    const float rscale = 0.08838834764831845f;
    size_t ibase = ((size_t)b * SS) * ld + (size_t)h * HD;
    size_t obase = ((size_t)b * SS) * DD + (size_t)h * HD;

#pragma unroll
    for (int i = 0; i < 16; i++) {
        int idx = i*256 + tid;
        int r = idx >> 5, c = (idx & 31)*4;
        float4 qv = *(const float4*)(Q + ibase + (size_t)(q0 + r)*ld + c);
        float* dst = Qs + r*QROWF + c;
        dst[0] = rtf32(qv.x*rscale); dst[1] = rtf32(qv.y*rscale);
        dst[2] = rtf32(qv.z*rscale); dst[3] = rtf32(qv.w*rscale);
    }

    float acc[16][4];
#pragma unroll
    for (int i = 0; i < 16; i++)
#pragma unroll
        for (int u = 0; u < 4; u++) acc[i][u] = 0.f;
    float m0r = -1e30f, m1r = -1e30f, l0r = 0.f, l1r = 0.f;
    const int qi0 = q0 + w*16 + r0;
    const int qi1 = qi0 + 8;

    const int nkt = (q0 >> 6) + 2;
    for (int kt = 0; kt < nkt; kt++) {
        int k0 = kt * 64;
        __syncthreads();
#pragma unroll
        for (int i = 0; i < 8; i++) {
            int idx = i*256 + tid;
            int r = idx >> 5, c = (idx & 31)*4;
            float4 kv = *(const float4*)(Kg + ibase + (size_t)(k0 + r)*ld + c);
            float* kd = Ks + r*QROWF + c;
            kd[0] = rtf32(kv.x); kd[1] = rtf32(kv.y);
            kd[2] = rtf32(kv.z); kd[3] = rtf32(kv.w);
            int vk = idx & 63, vd = (idx >> 6)*4;
            float4 vv = *(const float4*)(V + ibase + (size_t)(k0 + vk)*ld + vd);
            Vt[(vd+0)*VROWF + vk] = rtf32(vv.x);
            Vt[(vd+1)*VROWF + vk] = rtf32(vv.y);
            Vt[(vd+2)*VROWF + vk] = rtf32(vv.z);
            Vt[(vd+3)*VROWF + vk] = rtf32(vv.w);
        }
        __syncthreads();

        float s[8][4];
#pragma unroll
        for (int nt = 0; nt < 8; nt++)
#pragma unroll
            for (int u = 0; u < 4; u++) s[nt][u] = 0.f;
        const uint32_t* Qu = (const uint32_t*)Qs;
        const uint32_t* Ku = (const uint32_t*)Ks;
#pragma unroll
        for (int kc = 0; kc < 16; kc++) {
            int kb = kc*8;
            uint32_t a[4];
            int ra = (w*16 + r0)*QROWF + kb + c0;
            a[0] = Qu[ra];
            a[1] = Qu[ra + 8*QROWF];
            a[2] = Qu[ra + 4];
            a[3] = Qu[ra + 8*QROWF + 4];
#pragma unroll
            for (int nt = 0; nt < 8; nt++) {
                uint32_t bb[2];
                int rb = (nt*8 + r0)*QROWF + kb + c0;
                bb[0] = Ku[rb];
                bb[1] = Ku[rb + 4];
                mma_tf32(s[nt], a, bb);
            }
        }
        if (k0 + 63 > qi0) {
#pragma unroll
            for (int nt = 0; nt < 8; nt++) {
                int cj = k0 + nt*8 + 2*c0;
                if (cj     > qi0) s[nt][0] = -1e30f;
                if (cj + 1 > qi0) s[nt][1] = -1e30f;
                if (cj     > qi1) s[nt][2] = -1e30f;
                if (cj + 1 > qi1) s[nt][3] = -1e30f;
            }
        }
        float tm0 = -1e30f, tm1 = -1e30f;
#pragma unroll
        for (int nt = 0; nt < 8; nt++) {
            tm0 = fmaxf(tm0, fmaxf(s[nt][0], s[nt][1]));
            tm1 = fmaxf(tm1, fmaxf(s[nt][2], s[nt][3]));
        }
        tm0 = fmaxf(tm0, __shfl_xor_sync(0xFFFFFFFFu, tm0, 1));
        tm0 = fmaxf(tm0, __shfl_xor_sync(0xFFFFFFFFu, tm0, 2));
        tm1 = fmaxf(tm1, __shfl_xor_sync(0xFFFFFFFFu, tm1, 1));
        tm1 = fmaxf(tm1, __shfl_xor_sync(0xFFFFFFFFu, tm1, 2));
        float mn0 = fmaxf(m0r, tm0), f0 = __expf(m0r - mn0);
        float mn1 = fmaxf(m1r, tm1), f1 = __expf(m1r - mn1);
        float ps0 = 0.f, ps1 = 0.f;
#pragma unroll
        for (int nt = 0; nt < 8; nt++) {
            float p0 = __expf(s[nt][0] - mn0);
            float p1 = __expf(s[nt][1] - mn0);
            float p2 = __expf(s[nt][2] - mn1);
            float p3 = __expf(s[nt][3] - mn1);
            ps0 += p0 + p1; ps1 += p2 + p3;
            s[nt][0] = rtf32(p0); s[nt][1] = rtf32(p1);
            s[nt][2] = rtf32(p2); s[nt][3] = rtf32(p3);
        }
        ps0 += __shfl_xor_sync(0xFFFFFFFFu, ps0, 1);
        ps0 += __shfl_xor_sync(0xFFFFFFFFu, ps0, 2);
        ps1 += __shfl_xor_sync(0xFFFFFFFFu, ps1, 1);
        ps1 += __shfl_xor_sync(0xFFFFFFFFu, ps1, 2);
        l0r = l0r*f0 + ps0; m0r = mn0;
        l1r = l1r*f1 + ps1; m1r = mn1;
#pragma unroll
        for (int nt = 0; nt < 8; nt++) {
            int col = nt*8 + 2*c0;
            float2 p01; p01.x = s[nt][0]; p01.y = s[nt][1];
            float2 p23; p23.x = s[nt][2]; p23.y = s[nt][3];
            *(float2*)(Ps + (w*16 + r0    )*VROWF + col) = p01;
            *(float2*)(Ps + (w*16 + r0 + 8)*VROWF + col) = p23;
        }
        __syncwarp();
#pragma unroll
        for (int nt = 0; nt < 16; nt++) {
            acc[nt][0] *= f0; acc[nt][1] *= f0;
            acc[nt][2] *= f1; acc[nt][3] *= f1;
        }
        const uint32_t* Pu = (const uint32_t*)Ps;
        const uint32_t* Vu = (const uint32_t*)Vt;
#pragma unroll
        for (int kc = 0; kc < 8; kc++) {
            int kb = kc*8;
            uint32_t a[4];
            int ra = (w*16 + r0)*VROWF + kb + c0;
            a[0] = Pu[ra];
            a[1] = Pu[ra + 8*VROWF];
            a[2] = Pu[ra + 4];
            a[3] = Pu[ra + 8*VROWF + 4];
#pragma unroll
            for (int nt = 0; nt < 16; nt++) {
                uint32_t bb[2];
                int rb = (nt*8 + r0)*VROWF + kb + c0;
                bb[0] = Vu[rb];
                bb[1] = Vu[rb + 4];
                mma_tf32(acc[nt], a, bb);
            }
        }
    }

    float inv0 = 1.0f / l0r, inv1 = 1.0f / l1r;
#pragma unroll
    for (int nt = 0; nt < 16; nt++) {
        int n = nt*8 + 2*c0;
        float2 o0, o1;
        o0.x = rtf32(acc[nt][0]*inv0); o0.y = rtf32(acc[nt][1]*inv0);
        o1.x = rtf32(acc[nt][2]*inv1); o1.y = rtf32(acc[nt][3]*inv1);
        *(float2*)(O + obase + (size_t)qi0*DD + n) = o0;
        *(float2*)(O + obase + (size_t)qi1*DD + n) = o1;
    }
}

// ---------------- launch ----------------
extern "C" void kernel_launch(void* const* d_in, const int* in_sizes, int n_in,
                              void* d_out, int out_size) {
    const float* x    = (const float*)d_in[0];
    const float* Wq   = (const float*)d_in[1];
    const float* Wk   = (const float*)d_in[2];
    const float* Wv   = (const float*)d_in[3];
    const float* Wo   = (const float*)d_in[4];
    const float* bo   = (const float*)d_in[5];
    const float* ln1s = (const float*)d_in[6];
    const float* ln1b = (const float*)d_in[7];
    const float* ln2s = (const float*)d_in[8];
    const float* ln2b = (const float*)d_in[9];
    const float* W1   = (const float*)d_in[10];
    const float* b1   = (const float*)d_in[11];
    const float* W2   = (const float*)d_in[12];
    const float* b2   = (const float*)d_in[13];
    float* out = (float*)d_out;

    float *xn, *qkv, *ctx, *h, *ff, *wqkv, *wo, *w1, *w2;
    cudaGetSymbolAddress((void**)&xn,   g_xn);
    cudaGetSymbolAddress((void**)&qkv,  g_qkv);
    cudaGetSymbolAddress((void**)&ctx,  g_ctx);
    cudaGetSymbolAddress((void**)&h,    g_h);
    cudaGetSymbolAddress((void**)&ff,   g_ff);
    cudaGetSymbolAddress((void**)&wqkv, g_wqkv);
    cudaGetSymbolAddress((void**)&wo,   g_wo);
    cudaGetSymbolAddress((void**)&w1,   g_w1);
    cudaGetSymbolAddress((void**)&w2,   g_w2);

    cudaFuncSetAttribute(attn_mma, cudaFuncAttributeMaxDynamicSharedMemorySize, ATT_SMEM);
    cudaFuncSetAttribute(mma_gemm<0>, cudaFuncAttributeMaxDynamicSharedMemorySize, G_SMEM);
    cudaFuncSetAttribute(mma_gemm<1>, cudaFuncAttributeMaxDynamicSharedMemorySize, G_SMEM);
    cudaFuncSetAttribute(mma_gemm<2>, cudaFuncAttributeMaxDynamicSharedMemorySize, G_SMEM);

    const int n4a = DD*DD/4, n4b = DD*DFF/4;
    round_tf32_pack<<<(n4a+255)/256, 256>>>(Wq, wqkv, n4a, 0);
    round_tf32_pack<<<(n4a+255)/256, 256>>>(Wk, wqkv, n4a, 2048);
    round_tf32_pack<<<(n4a+255)/256, 256>>>(Wv, wqkv, n4a, 4096);
    round_tf32_kernel<<<(n4a+255)/256, 256>>>(Wo, wo, n4a);
    round_tf32_kernel<<<(n4b+255)/256, 256>>>(W1, w1, n4b);
    round_tf32_kernel<<<(n4b+255)/256, 256>>>(W2, w2, n4b);

    ln_kernel<<<MROW, 256>>>(x, ln1s, ln1b, xn);
    // fused QKV: [4096,2048] @ [2048,6144]
    mma_gemm<0><<<dim3(QS/256, MROW/128), 256, G_SMEM>>>(xn, wqkv, nullptr, nullptr, qkv, QS, DD);
    attn_mma<<<dim3(SS/128, BB*HH), 256, ATT_SMEM>>>(qkv, qkv + 2048, qkv + 4096, ctx, QS);
    mma_gemm<1><<<dim3(DD/256, MROW/128), 256, G_SMEM>>>(ctx, wo, bo, x, h, DD, DD);
    ln_kernel<<<MROW, 256>>>(h, ln2s, ln2b, xn);
    mma_gemm<2><<<dim3(DFF/256, MROW/128), 256, G_SMEM>>>(xn, w1, b1, nullptr, ff, DFF, DD);
    mma_gemm<1><<<dim3(DD/256, MROW/128), 256, G_SMEM>>>(ff, w2, b2, h, out, DD, DFF);
}

// round 8
// speedup vs baseline: 1.0779x; 1.0779x over previous
#include <cuda_runtime.h>
#include <math.h>
#include <stdint.h>

#define BB   2
#define SS   2048
#define DD   2048
#define HH   16
#define HD   128
#define DFF  8192
#define MROW 4096
#define QS   6144
#define EPSV 1e-5f

// ---------------- scratch ----------------
static __device__ float g_xn  [(size_t)MROW*DD];
static __device__ float g_qkv [(size_t)MROW*QS];
static __device__ float g_ctx [(size_t)MROW*DD];
static __device__ float g_h   [(size_t)MROW*DD];
static __device__ float g_ff  [(size_t)MROW*DFF];
// transposed + tf32-rounded weights: Wt[N][K]
static __device__ float g_wqkvT[(size_t)QS*DD];
static __device__ float g_woT  [(size_t)DD*DD];
static __device__ float g_w1T  [(size_t)DFF*DD];
static __device__ float g_w2T  [(size_t)DD*DFF];

// ---------------- helpers ----------------
__device__ __forceinline__ uint32_t smem_u32(const void* p) {
    uint32_t a;
    asm("{ .reg .u64 t; cvta.to.shared.u64 t, %1; cvt.u32.u64 %0, t; }" : "=r"(a) : "l"(p));
    return a;
}
__device__ __forceinline__ void cp_async16(uint32_t s, const void* g) {
    asm volatile("cp.async.cg.shared.global [%0], [%1], 16;" :: "r"(s), "l"(g));
}
__device__ __forceinline__ void cp_commit() {
    asm volatile("cp.async.commit_group;" ::: "memory");
}
__device__ __forceinline__ void cp_wait1() {
    asm volatile("cp.async.wait_group 1;" ::: "memory");
}
__device__ __forceinline__ float rtf32(float x) {
    uint32_t r;
    asm("cvt.rna.tf32.f32 %0, %1;" : "=r"(r) : "f"(x));
    return __uint_as_float(r);
}
__device__ __forceinline__ void ldmx4(uint32_t* r, uint32_t addr) {
    asm volatile("ldmatrix.sync.aligned.m8n8.x4.shared.b16 {%0,%1,%2,%3}, [%4];"
        : "=r"(r[0]), "=r"(r[1]), "=r"(r[2]), "=r"(r[3]) : "r"(addr));
}
__device__ __forceinline__ void mma_tf32(float* c, const uint32_t* a, const uint32_t* b) {
    asm volatile("mma.sync.aligned.m16n8k8.row.col.f32.tf32.tf32.f32 "
        "{%0,%1,%2,%3}, {%4,%5,%6,%7}, {%8,%9}, {%0,%1,%2,%3};"
        : "+f"(c[0]), "+f"(c[1]), "+f"(c[2]), "+f"(c[3])
        : "r"(a[0]), "r"(a[1]), "r"(a[2]), "r"(a[3]), "r"(b[0]), "r"(b[1]));
}
__device__ __forceinline__ float gelu_f(float x) {
    float x3 = x*x*x;
    return 0.5f * x * (1.0f + tanhf(0.79788456080286536f * (x + 0.044715f*x3)));
}

// ---------------- weight transpose + tf32 round ----------------
// W[K][N] -> Wt[rowOff + n][k] (ldOut = K), rounded
__global__ __launch_bounds__(256)
void transpose_round(const float* __restrict__ W, float* __restrict__ Wt,
                     int K, int N, int rowOff, int ldOut) {
    __shared__ float t[32][33];
    int k0 = blockIdx.y * 32, n0 = blockIdx.x * 32;
    int tx = threadIdx.x, ty = threadIdx.y;
#pragma unroll
    for (int i = 0; i < 4; i++)
        t[ty*4+i][tx] = W[(size_t)(k0 + ty*4 + i) * N + n0 + tx];
    __syncthreads();
#pragma unroll
    for (int i = 0; i < 4; i++)
        Wt[(size_t)(rowOff + n0 + ty*4 + i) * ldOut + k0 + tx] = rtf32(t[tx][ty*4+i]);
}

// ---------------- LayerNorm (tf32-rounded output) ----------------
__global__ __launch_bounds__(256)
void ln_kernel(const float* __restrict__ x, const float* __restrict__ sc,
               const float* __restrict__ sh, float* __restrict__ out) {
    int row = blockIdx.x;
    const float* xr = x + (size_t)row * DD;
    float v[8];
    float s = 0.f, sq = 0.f;
#pragma unroll
    for (int i = 0; i < 8; i++) {
        v[i] = xr[threadIdx.x + i*256];
        s += v[i]; sq += v[i]*v[i];
    }
    __shared__ float rs[8], rq[8];
    __shared__ float s_mean, s_rstd;
#pragma unroll
    for (int o = 16; o > 0; o >>= 1) {
        s  += __shfl_down_sync(0xFFFFFFFFu, s,  o);
        sq += __shfl_down_sync(0xFFFFFFFFu, sq, o);
    }
    int w = threadIdx.x >> 5;
    if ((threadIdx.x & 31) == 0) { rs[w] = s; rq[w] = sq; }
    __syncthreads();
    if (threadIdx.x == 0) {
        float ts = 0.f, tq = 0.f;
#pragma unroll
        for (int i = 0; i < 8; i++) { ts += rs[i]; tq += rq[i]; }
        float mean = ts * (1.0f/DD);
        s_mean = mean;
        s_rstd = rsqrtf(tq * (1.0f/DD) - mean*mean + EPSV);
    }
    __syncthreads();
    float mean = s_mean, rstd = s_rstd;
    float* orow = out + (size_t)row * DD;
#pragma unroll
    for (int i = 0; i < 8; i++) {
        int d = threadIdx.x + i*256;
        orow[d] = rtf32(sc[d]*(v[i]-mean)*rstd + sh[d]);
    }
}

// ---------------- TF32 GEMM: C[M,N] = A[M,K] @ Wt[N,K]^T ----------------
// CTA 128x128, 8 warps (2M x 4N), warp 64x32. ldmatrix fragment loads.
#define KSTEP   32
#define NSTG    3
#define ROWF    36                      // 32 data + 4 pad floats
#define T_BYTES (128*ROWF*4)            // 18432 (A tile == B tile)
#define STG_B   (2*T_BYTES)             // 36864
#define G_SMEM  (NSTG*STG_B)            // 110592

template<int EPI>
__global__ __launch_bounds__(256, 2)
void mma_gemm(const float* __restrict__ A, const float* __restrict__ Bt,
              const float* __restrict__ bias, const float* __restrict__ R,
              float* __restrict__ C, int N, int K) {
    extern __shared__ char dsm[];
    const int tid = threadIdx.x;
    const int lane = tid & 31;
    const int wid = tid >> 5;
    const int warpM = wid & 1;
    const int warpN = wid >> 1;
    const int m0 = blockIdx.y * 128;
    const int n0 = blockIdx.x * 128;
    const uint32_t sb = smem_u32(dsm);

    float acc[4][4][4];
#pragma unroll
    for (int i = 0; i < 4; i++)
#pragma unroll
        for (int j = 0; j < 4; j++)
#pragma unroll
            for (int u = 0; u < 4; u++) acc[i][j][u] = 0.f;

    const int NT = K / KSTEP;

    // producers: 128 rows x 32 floats per tile; 1024 chunks of 16B over 256 threads
    auto load_stage = [&](int s, int kk) {
        uint32_t ab = sb + s*STG_B;
        uint32_t bb = ab + T_BYTES;
#pragma unroll
        for (int i = 0; i < 4; i++) {
            int idx = i*256 + tid;
            int r = idx >> 3, c = idx & 7;
            cp_async16(ab + (r*ROWF + c*4)*4, A  + (size_t)(m0 + r)*K + kk + c*4);
            cp_async16(bb + (r*ROWF + c*4)*4, Bt + (size_t)(n0 + r)*K + kk + c*4);
        }
    };

    load_stage(0, 0); cp_commit();
    load_stage(1, KSTEP); cp_commit();

    // ldmatrix per-thread offsets
    const int j  = lane >> 3;        // tile index within x4
    const int rr = lane & 7;
    const uint32_t offA = ((warpM*64 + ((j&1)<<3) + rr) * ROWF + (j>>1)*4) * 4;
    const uint32_t offB = ((warpN*32 + (j>>1)*8  + rr) * ROWF + (j&1)*4) * 4;

    for (int t = 0; t < NT; t++) {
        cp_wait1();
        __syncthreads();
        if (t + 2 < NT) { load_stage((t+2)%NSTG, (t+2)*KSTEP); cp_commit(); }

        int s = t % NSTG;
        uint32_t abase = sb + s*STG_B + offA;
        uint32_t bbase = sb + s*STG_B + T_BYTES + offB;
#pragma unroll
        for (int k8 = 0; k8 < 4; k8++) {
            uint32_t ka = abase + k8*32;
            uint32_t kb = bbase + k8*32;
            uint32_t afr[4][4];
#pragma unroll
            for (int mt = 0; mt < 4; mt++)
                ldmx4(afr[mt], ka + mt*(16*ROWF*4));
            uint32_t bfr[4][2];
            ldmx4(&bfr[0][0], kb);
            ldmx4(&bfr[2][0], kb + 16*ROWF*4);
#pragma unroll
            for (int mt = 0; mt < 4; mt++)
#pragma unroll
                for (int nt = 0; nt < 4; nt++)
                    mma_tf32(acc[mt][nt], afr[mt], bfr[nt]);
        }
    }

#pragma unroll
    for (int mt = 0; mt < 4; mt++) {
#pragma unroll
        for (int half = 0; half < 2; half++) {
            int m = m0 + warpM*64 + mt*16 + (lane >> 2) + half*8;
#pragma unroll
            for (int nt = 0; nt < 4; nt++) {
                int n = n0 + warpN*32 + nt*8 + 2*(lane & 3);
                float v0 = acc[mt][nt][half*2 + 0];
                float v1 = acc[mt][nt][half*2 + 1];
                if (EPI == 1) {
                    const float2 bb = *(const float2*)(bias + n);
                    const float2 rrv = *(const float2*)(R + (size_t)m*N + n);
                    v0 += bb.x + rrv.x;
                    v1 += bb.y + rrv.y;
                } else if (EPI == 2) {
                    const float2 bb = *(const float2*)(bias + n);
                    v0 = rtf32(gelu_f(v0 + bb.x));
                    v1 = rtf32(gelu_f(v1 + bb.y));
                }
                float2 o; o.x = v0; o.y = v1;
                *(float2*)(C + (size_t)m*N + n) = o;
            }
        }
    }
}

// ---------------- causal flash attention (TF32 tensor cores) ----------------
#define QROWF 132
#define VROWF 68
#define ATT_SMEM ((128*QROWF + 64*QROWF + 128*VROWF + 128*VROWF) * 4)

__global__ __launch_bounds__(256, 1)
void attn_mma(const float* __restrict__ Q, const float* __restrict__ Kg,
              const float* __restrict__ V, float* __restrict__ O, int ld) {
    extern __shared__ float sm[];
    float* Qs = sm;
    float* Ks = Qs + 128*QROWF;
    float* Vt = Ks + 64*QROWF;
    float* Ps = Vt + 128*VROWF;

    const int tid = threadIdx.x;
    const int lane = tid & 31;
    const int w = tid >> 5;
    const int r0 = lane >> 2;
    const int c0 = lane & 3;
    const int q0 = blockIdx.x * 128;
    const int b = blockIdx.y >> 4;
    const int h = blockIdx.y & 15;
    const float rscale = 0.08838834764831845f;
    size_t ibase = ((size_t)b * SS) * ld + (size_t)h * HD;
    size_t obase = ((size_t)b * SS) * DD + (size_t)h * HD;

#pragma unroll
    for (int i = 0; i < 16; i++) {
        int idx = i*256 + tid;
        int r = idx >> 5, c = (idx & 31)*4;
        float4 qv = *(const float4*)(Q + ibase + (size_t)(q0 + r)*ld + c);
        float* dst = Qs + r*QROWF + c;
        dst[0] = rtf32(qv.x*rscale); dst[1] = rtf32(qv.y*rscale);
        dst[2] = rtf32(qv.z*rscale); dst[3] = rtf32(qv.w*rscale);
    }

    float acc[16][4];
#pragma unroll
    for (int i = 0; i < 16; i++)
#pragma unroll
        for (int u = 0; u < 4; u++) acc[i][u] = 0.f;
    float m0r = -1e30f, m1r = -1e30f, l0r = 0.f, l1r = 0.f;
    const int qi0 = q0 + w*16 + r0;
    const int qi1 = qi0 + 8;

    const int nkt = (q0 >> 6) + 2;
    for (int kt = 0; kt < nkt; kt++) {
        int k0 = kt * 64;
        __syncthreads();
#pragma unroll
        for (int i = 0; i < 8; i++) {
            int idx = i*256 + tid;
            int r = idx >> 5, c = (idx & 31)*4;
            float4 kv = *(const float4*)(Kg + ibase + (size_t)(k0 + r)*ld + c);
            float* kd = Ks + r*QROWF + c;
            kd[0] = rtf32(kv.x); kd[1] = rtf32(kv.y);
            kd[2] = rtf32(kv.z); kd[3] = rtf32(kv.w);
            int vk = idx & 63, vd = (idx >> 6)*4;
            float4 vv = *(const float4*)(V + ibase + (size_t)(k0 + vk)*ld + vd);
            Vt[(vd+0)*VROWF + vk] = rtf32(vv.x);
            Vt[(vd+1)*VROWF + vk] = rtf32(vv.y);
            Vt[(vd+2)*VROWF + vk] = rtf32(vv.z);
            Vt[(vd+3)*VROWF + vk] = rtf32(vv.w);
        }
        __syncthreads();

        float s[8][4];
#pragma unroll
        for (int nt = 0; nt < 8; nt++)
#pragma unroll
            for (int u = 0; u < 4; u++) s[nt][u] = 0.f;
        const uint32_t* Qu = (const uint32_t*)Qs;
        const uint32_t* Ku = (const uint32_t*)Ks;
#pragma unroll
        for (int kc = 0; kc < 16; kc++) {
            int kb = kc*8;
            uint32_t a[4];
            int ra = (w*16 + r0)*QROWF + kb + c0;
            a[0] = Qu[ra];
            a[1] = Qu[ra + 8*QROWF];
            a[2] = Qu[ra + 4];
            a[3] = Qu[ra + 8*QROWF + 4];
#pragma unroll
            for (int nt = 0; nt < 8; nt++) {
                uint32_t bb[2];
                int rb = (nt*8 + r0)*QROWF + kb + c0;
                bb[0] = Ku[rb];
                bb[1] = Ku[rb + 4];
                mma_tf32(s[nt], a, bb);
            }
        }
        if (k0 + 63 > qi0) {
#pragma unroll
            for (int nt = 0; nt < 8; nt++) {
                int cj = k0 + nt*8 + 2*c0;
                if (cj     > qi0) s[nt][0] = -1e30f;
                if (cj + 1 > qi0) s[nt][1] = -1e30f;
                if (cj     > qi1) s[nt][2] = -1e30f;
                if (cj + 1 > qi1) s[nt][3] = -1e30f;
            }
        }
        float tm0 = -1e30f, tm1 = -1e30f;
#pragma unroll
        for (int nt = 0; nt < 8; nt++) {
            tm0 = fmaxf(tm0, fmaxf(s[nt][0], s[nt][1]));
            tm1 = fmaxf(tm1, fmaxf(s[nt][2], s[nt][3]));
        }
        tm0 = fmaxf(tm0, __shfl_xor_sync(0xFFFFFFFFu, tm0, 1));
        tm0 = fmaxf(tm0, __shfl_xor_sync(0xFFFFFFFFu, tm0, 2));
        tm1 = fmaxf(tm1, __shfl_xor_sync(0xFFFFFFFFu, tm1, 1));
        tm1 = fmaxf(tm1, __shfl_xor_sync(0xFFFFFFFFu, tm1, 2));
        float mn0 = fmaxf(m0r, tm0), f0 = __expf(m0r - mn0);
        float mn1 = fmaxf(m1r, tm1), f1 = __expf(m1r - mn1);
        float ps0 = 0.f, ps1 = 0.f;
#pragma unroll
        for (int nt = 0; nt < 8; nt++) {
            float p0 = __expf(s[nt][0] - mn0);
            float p1 = __expf(s[nt][1] - mn0);
            float p2 = __expf(s[nt][2] - mn1);
            float p3 = __expf(s[nt][3] - mn1);
            ps0 += p0 + p1; ps1 += p2 + p3;
            s[nt][0] = rtf32(p0); s[nt][1] = rtf32(p1);
            s[nt][2] = rtf32(p2); s[nt][3] = rtf32(p3);
        }
        ps0 += __shfl_xor_sync(0xFFFFFFFFu, ps0, 1);
        ps0 += __shfl_xor_sync(0xFFFFFFFFu, ps0, 2);
        ps1 += __shfl_xor_sync(0xFFFFFFFFu, ps1, 1);
        ps1 += __shfl_xor_sync(0xFFFFFFFFu, ps1, 2);
        l0r = l0r*f0 + ps0; m0r = mn0;
        l1r = l1r*f1 + ps1; m1r = mn1;
#pragma unroll
        for (int nt = 0; nt < 8; nt++) {
            int col = nt*8 + 2*c0;
            float2 p01; p01.x = s[nt][0]; p01.y = s[nt][1];
            float2 p23; p23.x = s[nt][2]; p23.y = s[nt][3];
            *(float2*)(Ps + (w*16 + r0    )*VROWF + col) = p01;
            *(float2*)(Ps + (w*16 + r0 + 8)*VROWF + col) = p23;
        }
        __syncwarp();
#pragma unroll
        for (int nt = 0; nt < 16; nt++) {
            acc[nt][0] *= f0; acc[nt][1] *= f0;
            acc[nt][2] *= f1; acc[nt][3] *= f1;
        }
        const uint32_t* Pu = (const uint32_t*)Ps;
        const uint32_t* Vu = (const uint32_t*)Vt;
#pragma unroll
        for (int kc = 0; kc < 8; kc++) {
            int kb = kc*8;
            uint32_t a[4];
            int ra = (w*16 + r0)*VROWF + kb + c0;
            a[0] = Pu[ra];
            a[1] = Pu[ra + 8*VROWF];
            a[2] = Pu[ra + 4];
            a[3] = Pu[ra + 8*VROWF + 4];
#pragma unroll
            for (int nt = 0; nt < 16; nt++) {
                uint32_t bb[2];
                int rb = (nt*8 + r0)*VROWF + kb + c0;
                bb[0] = Vu[rb];
                bb[1] = Vu[rb + 4];
                mma_tf32(acc[nt], a, bb);
            }
        }
    }

    float inv0 = 1.0f / l0r, inv1 = 1.0f / l1r;
#pragma unroll
    for (int nt = 0; nt < 16; nt++) {
        int n = nt*8 + 2*c0;
        float2 o0, o1;
        o0.x = rtf32(acc[nt][0]*inv0); o0.y = rtf32(acc[nt][1]*inv0);
        o1.x = rtf32(acc[nt][2]*inv1); o1.y = rtf32(acc[nt][3]*inv1);
        *(float2*)(O + obase + (size_t)qi0*DD + n) = o0;
        *(float2*)(O + obase + (size_t)qi1*DD + n) = o1;
    }
}

// ---------------- launch ----------------
extern "C" void kernel_launch(void* const* d_in, const int* in_sizes, int n_in,
                              void* d_out, int out_size) {
    const float* x    = (const float*)d_in[0];
    const float* Wq   = (const float*)d_in[1];
    const float* Wk   = (const float*)d_in[2];
    const float* Wv   = (const float*)d_in[3];
    const float* Wo   = (const float*)d_in[4];
    const float* bo   = (const float*)d_in[5];
    const float* ln1s = (const float*)d_in[6];
    const float* ln1b = (const float*)d_in[7];
    const float* ln2s = (const float*)d_in[8];
    const float* ln2b = (const float*)d_in[9];
    const float* W1   = (const float*)d_in[10];
    const float* b1   = (const float*)d_in[11];
    const float* W2   = (const float*)d_in[12];
    const float* b2   = (const float*)d_in[13];
    float* out = (float*)d_out;

    float *xn, *qkv, *ctx, *h, *ff, *wqkvT, *woT, *w1T, *w2T;
    cudaGetSymbolAddress((void**)&xn,    g_xn);
    cudaGetSymbolAddress((void**)&qkv,   g_qkv);
    cudaGetSymbolAddress((void**)&ctx,   g_ctx);
    cudaGetSymbolAddress((void**)&h,     g_h);
    cudaGetSymbolAddress((void**)&ff,    g_ff);
    cudaGetSymbolAddress((void**)&wqkvT, g_wqkvT);
    cudaGetSymbolAddress((void**)&woT,   g_woT);
    cudaGetSymbolAddress((void**)&w1T,   g_w1T);
    cudaGetSymbolAddress((void**)&w2T,   g_w2T);

    cudaFuncSetAttribute(attn_mma, cudaFuncAttributeMaxDynamicSharedMemorySize, ATT_SMEM);
    cudaFuncSetAttribute(mma_gemm<0>, cudaFuncAttributeMaxDynamicSharedMemorySize, G_SMEM);
    cudaFuncSetAttribute(mma_gemm<1>, cudaFuncAttributeMaxDynamicSharedMemorySize, G_SMEM);
    cudaFuncSetAttribute(mma_gemm<2>, cudaFuncAttributeMaxDynamicSharedMemorySize, G_SMEM);

    dim3 t32(32, 8);
    // weight transposes + tf32 round: W[K][N] -> Wt[N][K]
    transpose_round<<<dim3(DD/32,  DD/32), t32>>>(Wq, wqkvT, DD, DD, 0,    DD);
    transpose_round<<<dim3(DD/32,  DD/32), t32>>>(Wk, wqkvT, DD, DD, 2048, DD);
    transpose_round<<<dim3(DD/32,  DD/32), t32>>>(Wv, wqkvT, DD, DD, 4096, DD);
    transpose_round<<<dim3(DD/32,  DD/32), t32>>>(Wo, woT, DD, DD, 0, DD);
    transpose_round<<<dim3(DFF/32, DD/32), t32>>>(W1, w1T, DD, DFF, 0, DD);
    transpose_round<<<dim3(DD/32, DFF/32), t32>>>(W2, w2T, DFF, DD, 0, DFF);

    ln_kernel<<<MROW, 256>>>(x, ln1s, ln1b, xn);
    // fused QKV: [4096,2048] @ [2048,6144]
    mma_gemm<0><<<dim3(QS/128, MROW/128), 256, G_SMEM>>>(xn, wqkvT, nullptr, nullptr, qkv, QS, DD);
    attn_mma<<<dim3(SS/128, BB*HH), 256, ATT_SMEM>>>(qkv, qkv + 2048, qkv + 4096, ctx, QS);
    mma_gemm<1><<<dim3(DD/128, MROW/128), 256, G_SMEM>>>(ctx, woT, bo, x, h, DD, DD);
    ln_kernel<<<MROW, 256>>>(h, ln2s, ln2b, xn);
    mma_gemm<2><<<dim3(DFF/128, MROW/128), 256, G_SMEM>>>(xn, w1T, b1, nullptr, ff, DFF, DD);
    mma_gemm<1><<<dim3(DD/128, MROW/128), 256, G_SMEM>>>(ff, w2T, b2, h, out, DD, DFF);
}

// round 9
// speedup vs baseline: 2.0461x; 1.8982x over previous
#include <cuda_runtime.h>
#include <cuda_fp16.h>
#include <math.h>
#include <stdint.h>

#define BB   2
#define SS   2048
#define DD   2048
#define HH   16
#define HD   128
#define DFF  8192
#define MROW 4096
#define QS   6144
#define EPSV 1e-5f

// ---------------- scratch ----------------
static __device__ __half g_xn  [(size_t)MROW*DD];
static __device__ __half g_qkv [(size_t)MROW*QS];
static __device__ __half g_ctx [(size_t)MROW*DD];
static __device__ float  g_h   [(size_t)MROW*DD];
static __device__ __half g_ff  [(size_t)MROW*DFF];
// transposed fp16 weights Wt[N][K]
static __device__ __half g_wqkvT[(size_t)QS*DD];
static __device__ __half g_woT  [(size_t)DD*DD];
static __device__ __half g_w1T  [(size_t)DFF*DD];
static __device__ __half g_w2T  [(size_t)DD*DFF];

// ---------------- helpers ----------------
__device__ __forceinline__ uint32_t smem_u32(const void* p) {
    uint32_t a;
    asm("{ .reg .u64 t; cvta.to.shared.u64 t, %1; cvt.u32.u64 %0, t; }" : "=r"(a) : "l"(p));
    return a;
}
__device__ __forceinline__ void cp_async16(uint32_t s, const void* g) {
    asm volatile("cp.async.cg.shared.global [%0], [%1], 16;" :: "r"(s), "l"(g));
}
__device__ __forceinline__ void cp_commit() {
    asm volatile("cp.async.commit_group;" ::: "memory");
}
__device__ __forceinline__ void cp_wait1() {
    asm volatile("cp.async.wait_group 1;" ::: "memory");
}
__device__ __forceinline__ void ldmx4(uint32_t* r, uint32_t addr) {
    asm volatile("ldmatrix.sync.aligned.m8n8.x4.shared.b16 {%0,%1,%2,%3}, [%4];"
        : "=r"(r[0]), "=r"(r[1]), "=r"(r[2]), "=r"(r[3]) : "r"(addr));
}
__device__ __forceinline__ void ldmx4t(uint32_t* r, uint32_t addr) {
    asm volatile("ldmatrix.sync.aligned.m8n8.x4.trans.shared.b16 {%0,%1,%2,%3}, [%4];"
        : "=r"(r[0]), "=r"(r[1]), "=r"(r[2]), "=r"(r[3]) : "r"(addr));
}
__device__ __forceinline__ void mma_f16(float* c, const uint32_t* a, const uint32_t* b) {
    asm volatile("mma.sync.aligned.m16n8k16.row.col.f32.f16.f16.f32 "
        "{%0,%1,%2,%3}, {%4,%5,%6,%7}, {%8,%9}, {%0,%1,%2,%3};"
        : "+f"(c[0]), "+f"(c[1]), "+f"(c[2]), "+f"(c[3])
        : "r"(a[0]), "r"(a[1]), "r"(a[2]), "r"(a[3]), "r"(b[0]), "r"(b[1]));
}
__device__ __forceinline__ float gelu_f(float x) {
    float x3 = x*x*x;
    return 0.5f * x * (1.0f + tanhf(0.79788456080286536f * (x + 0.044715f*x3)));
}

// ---------------- weight transpose -> fp16 ----------------
// W[K][N] fp32 -> Wt[rowOff + n][k] half (ldOut = K)
__global__ __launch_bounds__(256)
void transpose_half(const float* __restrict__ W, __half* __restrict__ Wt,
                    int K, int N, int rowOff, int ldOut) {
    __shared__ float t[32][33];
    int k0 = blockIdx.y * 32, n0 = blockIdx.x * 32;
    int tx = threadIdx.x, ty = threadIdx.y;
#pragma unroll
    for (int i = 0; i < 4; i++)
        t[ty*4+i][tx] = W[(size_t)(k0 + ty*4 + i) * N + n0 + tx];
    __syncthreads();
#pragma unroll
    for (int i = 0; i < 4; i++)
        Wt[(size_t)(rowOff + n0 + ty*4 + i) * ldOut + k0 + tx] = __float2half(t[tx][ty*4+i]);
}

// ---------------- LayerNorm (fp32 in -> fp16 out) ----------------
__global__ __launch_bounds__(256)
void ln_kernel(const float* __restrict__ x, const float* __restrict__ sc,
               const float* __restrict__ sh, __half* __restrict__ out) {
    int row = blockIdx.x;
    const float* xr = x + (size_t)row * DD;
    float v[8];
    float s = 0.f, sq = 0.f;
#pragma unroll
    for (int i = 0; i < 8; i++) {
        v[i] = xr[threadIdx.x + i*256];
        s += v[i]; sq += v[i]*v[i];
    }
    __shared__ float rs[8], rq[8];
    __shared__ float s_mean, s_rstd;
#pragma unroll
    for (int o = 16; o > 0; o >>= 1) {
        s  += __shfl_down_sync(0xFFFFFFFFu, s,  o);
        sq += __shfl_down_sync(0xFFFFFFFFu, sq, o);
    }
    int w = threadIdx.x >> 5;
    if ((threadIdx.x & 31) == 0) { rs[w] = s; rq[w] = sq; }
    __syncthreads();
    if (threadIdx.x == 0) {
        float ts = 0.f, tq = 0.f;
#pragma unroll
        for (int i = 0; i < 8; i++) { ts += rs[i]; tq += rq[i]; }
        float mean = ts * (1.0f/DD);
        s_mean = mean;
        s_rstd = rsqrtf(tq * (1.0f/DD) - mean*mean + EPSV);
    }
    __syncthreads();
    float mean = s_mean, rstd = s_rstd;
    __half* orow = out + (size_t)row * DD;
#pragma unroll
    for (int i = 0; i < 8; i++) {
        int d = threadIdx.x + i*256;
        orow[d] = __float2half(sc[d]*(v[i]-mean)*rstd + sh[d]);
    }
}

// ---------------- FP16 GEMM: C = A[M,K] @ Wt[N,K]^T ----------------
// CTA 128x128, 8 warps (2M x 4N), warp 64x32, KSTEP=64, 3-stage cp.async.
#define KSTEP   64
#define ROWH    72                       // 64 data halfs + 8 pad (144B, 9x16B)
#define T_BYTES (128*ROWH*2)             // 18432
#define STG_B   (2*T_BYTES)              // 36864
#define G_SMEM  (3*STG_B)                // 110592

// EPI 0: Ch = acc (half)   EPI 1: Cf = acc+bias+R (fp32)   EPI 2: Ch = gelu(acc+bias) (half)
template<int EPI>
__global__ __launch_bounds__(256, 2)
void mma_gemm(const __half* __restrict__ A, const __half* __restrict__ Bt,
              const float* __restrict__ bias, const float* __restrict__ R,
              float* __restrict__ Cf, __half* __restrict__ Ch, int N, int K) {
    extern __shared__ char dsm[];
    const int tid = threadIdx.x;
    const int lane = tid & 31;
    const int wid = tid >> 5;
    const int warpM = wid & 1;
    const int warpN = wid >> 1;
    const int m0 = blockIdx.y * 128;
    const int n0 = blockIdx.x * 128;
    const uint32_t sb = smem_u32(dsm);

    float acc[4][4][4];
#pragma unroll
    for (int i = 0; i < 4; i++)
#pragma unroll
        for (int j = 0; j < 4; j++)
#pragma unroll
            for (int u = 0; u < 4; u++) acc[i][j][u] = 0.f;

    const int NT = K / KSTEP;

    auto load_stage = [&](int s, int kk) {
        uint32_t ab = sb + s*STG_B;
        uint32_t bb = ab + T_BYTES;
#pragma unroll
        for (int i = 0; i < 4; i++) {
            int idx = i*256 + tid;
            int r = idx >> 3, c = idx & 7;
            cp_async16(ab + (r*ROWH + c*8)*2, A  + (size_t)(m0 + r)*K + kk + c*8);
            cp_async16(bb + (r*ROWH + c*8)*2, Bt + (size_t)(n0 + r)*K + kk + c*8);
        }
    };

    load_stage(0, 0); cp_commit();
    load_stage(1, KSTEP); cp_commit();

    const int j  = lane >> 3;
    const int rr = lane & 7;
    const uint32_t offA = ((warpM*64 + ((j&1)<<3) + rr) * ROWH + (j>>1)*8) * 2;
    const uint32_t offB = ((warpN*32 + (j>>1)*8  + rr) * ROWH + (j&1)*8) * 2;

    for (int t = 0; t < NT; t++) {
        cp_wait1();
        __syncthreads();
        if (t + 2 < NT) { load_stage((t+2)%3, (t+2)*KSTEP); cp_commit(); }

        int s = t % 3;
        uint32_t abase = sb + s*STG_B + offA;
        uint32_t bbase = sb + s*STG_B + T_BYTES + offB;
#pragma unroll
        for (int k16 = 0; k16 < 4; k16++) {
            uint32_t ka = abase + k16*32;
            uint32_t kb = bbase + k16*32;
            uint32_t afr[4][4];
#pragma unroll
            for (int mt = 0; mt < 4; mt++)
                ldmx4(afr[mt], ka + mt*(16*ROWH*2));
            uint32_t bfr[4][2];
            ldmx4(&bfr[0][0], kb);
            ldmx4(&bfr[2][0], kb + 16*ROWH*2);
#pragma unroll
            for (int mt = 0; mt < 4; mt++)
#pragma unroll
                for (int nt = 0; nt < 4; nt++)
                    mma_f16(acc[mt][nt], afr[mt], bfr[nt]);
        }
    }

#pragma unroll
    for (int mt = 0; mt < 4; mt++) {
#pragma unroll
        for (int half_ = 0; half_ < 2; half_++) {
            int m = m0 + warpM*64 + mt*16 + (lane >> 2) + half_*8;
#pragma unroll
            for (int nt = 0; nt < 4; nt++) {
                int n = n0 + warpN*32 + nt*8 + 2*(lane & 3);
                float v0 = acc[mt][nt][half_*2 + 0];
                float v1 = acc[mt][nt][half_*2 + 1];
                if (EPI == 0) {
                    *(__half2*)(Ch + (size_t)m*N + n) = __floats2half2_rn(v0, v1);
                } else if (EPI == 1) {
                    const float2 bb = *(const float2*)(bias + n);
                    const float2 rv = *(const float2*)(R + (size_t)m*N + n);
                    float2 o; o.x = v0 + bb.x + rv.x; o.y = v1 + bb.y + rv.y;
                    *(float2*)(Cf + (size_t)m*N + n) = o;
                } else {
                    const float2 bb = *(const float2*)(bias + n);
                    *(__half2*)(Ch + (size_t)m*N + n) =
                        __floats2half2_rn(gelu_f(v0 + bb.x), gelu_f(v1 + bb.y));
                }
            }
        }
    }
}

// ---------------- causal flash attention (fp16 tensor cores) ----------------
// 256 threads / 8 warps; Q tile 128 (16 rows per warp), K tile 64.
#define QROWH 136                        // 128 + 8 pad halfs (272B = 17x16B)
#define PROWH 72                         // 64 + 8 pad halfs (144B)
#define ATT_SMEM ((128*QROWH + 64*QROWH + 64*QROWH + 128*PROWH) * 2)

__global__ __launch_bounds__(256)
void attn_mma(const __half* __restrict__ Q, const __half* __restrict__ Kg,
              const __half* __restrict__ V, __half* __restrict__ O, int ld) {
    extern __shared__ __half hsm[];
    __half* Qs = hsm;                    // [128][136]
    __half* Ks = Qs + 128*QROWH;         // [64][136]
    __half* Vs = Ks + 64*QROWH;          // [64][136]  (row = key, cols = d)
    __half* Ps = Vs + 64*QROWH;          // [128][72]

    const int tid = threadIdx.x;
    const int lane = tid & 31;
    const int w = tid >> 5;
    const int r0 = lane >> 2;
    const int c0 = lane & 3;
    const int j  = lane >> 3;
    const int rr = lane & 7;
    const int q0 = blockIdx.x * 128;
    const int b = blockIdx.y >> 4;
    const int h = blockIdx.y & 15;
    const float rscale = 0.08838834764831845f;
    size_t ibase = ((size_t)b * SS) * ld + (size_t)h * HD;
    size_t obase = ((size_t)b * SS) * DD + (size_t)h * HD;

    // Q tile: raw half copy (scale folded into softmax)
#pragma unroll
    for (int i = 0; i < 8; i++) {
        int idx = i*256 + tid;
        int r = idx >> 4, c = (idx & 15)*8;
        *(uint4*)(Qs + r*QROWH + c) = *(const uint4*)(Q + ibase + (size_t)(q0 + r)*ld + c);
    }

    float acc[16][4];
#pragma unroll
    for (int i = 0; i < 16; i++)
#pragma unroll
        for (int u = 0; u < 4; u++) acc[i][u] = 0.f;
    float m0r = -1e30f, m1r = -1e30f, l0r = 0.f, l1r = 0.f;
    const int qi0 = q0 + w*16 + r0;
    const int qi1 = qi0 + 8;

    const uint32_t sQ = smem_u32(Qs), sK = smem_u32(Ks), sV = smem_u32(Vs), sP = smem_u32(Ps);
    const uint32_t offQ = ((w*16 + ((j&1)<<3) + rr)*QROWH + (j>>1)*8)*2;
    const uint32_t offK = (((j>>1)*8 + rr)*QROWH + (j&1)*8)*2;
    const uint32_t offP = ((w*16 + ((j&1)<<3) + rr)*PROWH + (j>>1)*8)*2;
    const uint32_t offV = (((j&1)*8 + rr)*QROWH + (j>>1)*8)*2;

    const int nkt = (q0 >> 6) + 2;
    for (int kt = 0; kt < nkt; kt++) {
        int k0 = kt * 64;
        __syncthreads();
#pragma unroll
        for (int i = 0; i < 4; i++) {
            int idx = i*256 + tid;
            int r = idx >> 4, c = (idx & 15)*8;
            *(uint4*)(Ks + r*QROWH + c) = *(const uint4*)(Kg + ibase + (size_t)(k0 + r)*ld + c);
            *(uint4*)(Vs + r*QROWH + c) = *(const uint4*)(V  + ibase + (size_t)(k0 + r)*ld + c);
        }
        __syncthreads();

        // S = Q @ K^T
        float s[8][4];
#pragma unroll
        for (int nt = 0; nt < 8; nt++)
#pragma unroll
            for (int u = 0; u < 4; u++) s[nt][u] = 0.f;
#pragma unroll
        for (int kc = 0; kc < 8; kc++) {
            uint32_t a[4];
            ldmx4(a, sQ + offQ + kc*32);
#pragma unroll
            for (int g = 0; g < 4; g++) {
                uint32_t bb[4];
                ldmx4(bb, sK + offK + kc*32 + g*(16*QROWH*2));
                mma_f16(s[2*g    ], a, bb);
                mma_f16(s[2*g + 1], a, bb + 2);
            }
        }
        // scale + causal mask
#pragma unroll
        for (int nt = 0; nt < 8; nt++)
#pragma unroll
            for (int u = 0; u < 4; u++) s[nt][u] *= rscale;
        if (k0 + 63 > qi0) {
#pragma unroll
            for (int nt = 0; nt < 8; nt++) {
                int cj = k0 + nt*8 + 2*c0;
                if (cj     > qi0) s[nt][0] = -1e30f;
                if (cj + 1 > qi0) s[nt][1] = -1e30f;
                if (cj     > qi1) s[nt][2] = -1e30f;
                if (cj + 1 > qi1) s[nt][3] = -1e30f;
            }
        }
        // online softmax
        float tm0 = -1e30f, tm1 = -1e30f;
#pragma unroll
        for (int nt = 0; nt < 8; nt++) {
            tm0 = fmaxf(tm0, fmaxf(s[nt][0], s[nt][1]));
            tm1 = fmaxf(tm1, fmaxf(s[nt][2], s[nt][3]));
        }
        tm0 = fmaxf(tm0, __shfl_xor_sync(0xFFFFFFFFu, tm0, 1));
        tm0 = fmaxf(tm0, __shfl_xor_sync(0xFFFFFFFFu, tm0, 2));
        tm1 = fmaxf(tm1, __shfl_xor_sync(0xFFFFFFFFu, tm1, 1));
        tm1 = fmaxf(tm1, __shfl_xor_sync(0xFFFFFFFFu, tm1, 2));
        float mn0 = fmaxf(m0r, tm0), f0 = __expf(m0r - mn0);
        float mn1 = fmaxf(m1r, tm1), f1 = __expf(m1r - mn1);
        float ps0 = 0.f, ps1 = 0.f;
#pragma unroll
        for (int nt = 0; nt < 8; nt++) {
            float p0 = __expf(s[nt][0] - mn0);
            float p1 = __expf(s[nt][1] - mn0);
            float p2 = __expf(s[nt][2] - mn1);
            float p3 = __expf(s[nt][3] - mn1);
            ps0 += p0 + p1; ps1 += p2 + p3;
            int col = nt*8 + 2*c0;
            *(__half2*)(Ps + (w*16 + r0    )*PROWH + col) = __floats2half2_rn(p0, p1);
            *(__half2*)(Ps + (w*16 + r0 + 8)*PROWH + col) = __floats2half2_rn(p2, p3);
        }
        ps0 += __shfl_xor_sync(0xFFFFFFFFu, ps0, 1);
        ps0 += __shfl_xor_sync(0xFFFFFFFFu, ps0, 2);
        ps1 += __shfl_xor_sync(0xFFFFFFFFu, ps1, 1);
        ps1 += __shfl_xor_sync(0xFFFFFFFFu, ps1, 2);
        l0r = l0r*f0 + ps0; m0r = mn0;
        l1r = l1r*f1 + ps1; m1r = mn1;
        __syncwarp();
#pragma unroll
        for (int nt = 0; nt < 16; nt++) {
            acc[nt][0] *= f0; acc[nt][1] *= f0;
            acc[nt][2] *= f1; acc[nt][3] *= f1;
        }
        // O += P @ V  (B frags via ldmatrix.trans on Vs[key][d])
#pragma unroll
        for (int kc = 0; kc < 4; kc++) {
            uint32_t a[4];
            ldmx4(a, sP + offP + kc*32);
#pragma unroll
            for (int g = 0; g < 8; g++) {
                uint32_t bb[4];
                ldmx4t(bb, sV + offV + kc*(16*QROWH*2) + g*32);
                mma_f16(acc[2*g    ], a, bb);
                mma_f16(acc[2*g + 1], a, bb + 2);
            }
        }
    }

    float inv0 = 1.0f / l0r, inv1 = 1.0f / l1r;
#pragma unroll
    for (int nt = 0; nt < 16; nt++) {
        int n = nt*8 + 2*c0;
        *(__half2*)(O + obase + (size_t)qi0*DD + n) = __floats2half2_rn(acc[nt][0]*inv0, acc[nt][1]*inv0);
        *(__half2*)(O + obase + (size_t)qi1*DD + n) = __floats2half2_rn(acc[nt][2]*inv1, acc[nt][3]*inv1);
    }
}

// ---------------- launch ----------------
extern "C" void kernel_launch(void* const* d_in, const int* in_sizes, int n_in,
                              void* d_out, int out_size) {
    const float* x    = (const float*)d_in[0];
    const float* Wq   = (const float*)d_in[1];
    const float* Wk   = (const float*)d_in[2];
    const float* Wv   = (const float*)d_in[3];
    const float* Wo   = (const float*)d_in[4];
    const float* bo   = (const float*)d_in[5];
    const float* ln1s = (const float*)d_in[6];
    const float* ln1b = (const float*)d_in[7];
    const float* ln2s = (const float*)d_in[8];
    const float* ln2b = (const float*)d_in[9];
    const float* W1   = (const float*)d_in[10];
    const float* b1   = (const float*)d_in[11];
    const float* W2   = (const float*)d_in[12];
    const float* b2   = (const float*)d_in[13];
    float* out = (float*)d_out;

    __half *xn, *qkv, *ctx, *ff, *wqkvT, *woT, *w1T, *w2T;
    float* h;
    cudaGetSymbolAddress((void**)&xn,    g_xn);
    cudaGetSymbolAddress((void**)&qkv,   g_qkv);
    cudaGetSymbolAddress((void**)&ctx,   g_ctx);
    cudaGetSymbolAddress((void**)&h,     g_h);
    cudaGetSymbolAddress((void**)&ff,    g_ff);
    cudaGetSymbolAddress((void**)&wqkvT, g_wqkvT);
    cudaGetSymbolAddress((void**)&woT,   g_woT);
    cudaGetSymbolAddress((void**)&w1T,   g_w1T);
    cudaGetSymbolAddress((void**)&w2T,   g_w2T);

    cudaFuncSetAttribute(attn_mma, cudaFuncAttributeMaxDynamicSharedMemorySize, ATT_SMEM);
    cudaFuncSetAttribute(mma_gemm<0>, cudaFuncAttributeMaxDynamicSharedMemorySize, G_SMEM);
    cudaFuncSetAttribute(mma_gemm<1>, cudaFuncAttributeMaxDynamicSharedMemorySize, G_SMEM);
    cudaFuncSetAttribute(mma_gemm<2>, cudaFuncAttributeMaxDynamicSharedMemorySize, G_SMEM);

    dim3 t32(32, 8);
    transpose_half<<<dim3(DD/32,  DD/32), t32>>>(Wq, wqkvT, DD, DD, 0,    DD);
    transpose_half<<<dim3(DD/32,  DD/32), t32>>>(Wk, wqkvT, DD, DD, 2048, DD);
    transpose_half<<<dim3(DD/32,  DD/32), t32>>>(Wv, wqkvT, DD, DD, 4096, DD);
    transpose_half<<<dim3(DD/32,  DD/32), t32>>>(Wo, woT, DD, DD, 0, DD);
    transpose_half<<<dim3(DFF/32, DD/32), t32>>>(W1, w1T, DD, DFF, 0, DD);
    transpose_half<<<dim3(DD/32, DFF/32), t32>>>(W2, w2T, DFF, DD, 0, DFF);

    ln_kernel<<<MROW, 256>>>(x, ln1s, ln1b, xn);
    // fused QKV: [4096,2048] @ [2048,6144] -> half
    mma_gemm<0><<<dim3(QS/128, MROW/128), 256, G_SMEM>>>(
        xn, wqkvT, nullptr, nullptr, nullptr, qkv, QS, DD);
    attn_mma<<<dim3(SS/128, BB*HH), 256, ATT_SMEM>>>(qkv, qkv + 2048, qkv + 4096, ctx, QS);
    mma_gemm<1><<<dim3(DD/128, MROW/128), 256, G_SMEM>>>(
        ctx, woT, bo, x, h, nullptr, DD, DD);
    ln_kernel<<<MROW, 256>>>(h, ln2s, ln2b, xn);
    mma_gemm<2><<<dim3(DFF/128, MROW/128), 256, G_SMEM>>>(
        xn, w1T, b1, nullptr, nullptr, ff, DFF, DD);
    mma_gemm<1><<<dim3(DD/128, MROW/128), 256, G_SMEM>>>(
        ff, w2T, b2, h, out, nullptr, DD, DFF);
}

// round 10
// speedup vs baseline: 2.1218x; 1.0370x over previous
#include <cuda_runtime.h>
#include <cuda_fp16.h>
#include <math.h>
#include <stdint.h>

#define BB   2
#define SS   2048
#define DD   2048
#define HH   16
#define HD   128
#define DFF  8192
#define MROW 4096
#define QS   6144
#define EPSV 1e-5f

// ---------------- scratch ----------------
static __device__ __half g_xn  [(size_t)MROW*DD];
static __device__ __half g_qkv [(size_t)MROW*QS];
static __device__ __half g_ctx [(size_t)MROW*DD];
static __device__ float  g_h   [(size_t)MROW*DD];
static __device__ __half g_ff  [(size_t)MROW*DFF];
static __device__ __half g_wqkvT[(size_t)QS*DD];
static __device__ __half g_woT  [(size_t)DD*DD];
static __device__ __half g_w1T  [(size_t)DFF*DD];
static __device__ __half g_w2T  [(size_t)DD*DFF];

// ---------------- helpers ----------------
__device__ __forceinline__ uint32_t smem_u32(const void* p) {
    uint32_t a;
    asm("{ .reg .u64 t; cvta.to.shared.u64 t, %1; cvt.u32.u64 %0, t; }" : "=r"(a) : "l"(p));
    return a;
}
__device__ __forceinline__ void cp_async16(uint32_t s, const void* g) {
    asm volatile("cp.async.cg.shared.global [%0], [%1], 16;" :: "r"(s), "l"(g));
}
__device__ __forceinline__ void cp_commit() {
    asm volatile("cp.async.commit_group;" ::: "memory");
}
__device__ __forceinline__ void cp_wait1() {
    asm volatile("cp.async.wait_group 1;" ::: "memory");
}
__device__ __forceinline__ void cp_wait0() {
    asm volatile("cp.async.wait_group 0;" ::: "memory");
}
__device__ __forceinline__ void ldmx4(uint32_t* r, uint32_t addr) {
    asm volatile("ldmatrix.sync.aligned.m8n8.x4.shared.b16 {%0,%1,%2,%3}, [%4];"
        : "=r"(r[0]), "=r"(r[1]), "=r"(r[2]), "=r"(r[3]) : "r"(addr));
}
__device__ __forceinline__ void ldmx4t(uint32_t* r, uint32_t addr) {
    asm volatile("ldmatrix.sync.aligned.m8n8.x4.trans.shared.b16 {%0,%1,%2,%3}, [%4];"
        : "=r"(r[0]), "=r"(r[1]), "=r"(r[2]), "=r"(r[3]) : "r"(addr));
}
__device__ __forceinline__ void mma_f16(float* c, const uint32_t* a, const uint32_t* b) {
    asm volatile("mma.sync.aligned.m16n8k16.row.col.f32.f16.f16.f32 "
        "{%0,%1,%2,%3}, {%4,%5,%6,%7}, {%8,%9}, {%0,%1,%2,%3};"
        : "+f"(c[0]), "+f"(c[1]), "+f"(c[2]), "+f"(c[3])
        : "r"(a[0]), "r"(a[1]), "r"(a[2]), "r"(a[3]), "r"(b[0]), "r"(b[1]));
}
__device__ __forceinline__ uint32_t pack_h2(float a, float b) {
    __half2 t = __floats2half2_rn(a, b);
    return *reinterpret_cast<uint32_t*>(&t);
}
__device__ __forceinline__ float gelu_f(float x) {
    float x3 = x*x*x;
    return 0.5f * x * (1.0f + tanhf(0.79788456080286536f * (x + 0.044715f*x3)));
}

// ---------------- weight transpose -> fp16 ----------------
__global__ __launch_bounds__(256)
void transpose_half(const float* __restrict__ W, __half* __restrict__ Wt,
                    int K, int N, int rowOff, int ldOut) {
    __shared__ float t[32][33];
    int k0 = blockIdx.y * 32, n0 = blockIdx.x * 32;
    int tx = threadIdx.x, ty = threadIdx.y;
#pragma unroll
    for (int i = 0; i < 4; i++)
        t[ty*4+i][tx] = W[(size_t)(k0 + ty*4 + i) * N + n0 + tx];
    __syncthreads();
#pragma unroll
    for (int i = 0; i < 4; i++)
        Wt[(size_t)(rowOff + n0 + ty*4 + i) * ldOut + k0 + tx] = __float2half(t[tx][ty*4+i]);
}

// ---------------- LayerNorm (fp32 in -> fp16 out) ----------------
__global__ __launch_bounds__(256)
void ln_kernel(const float* __restrict__ x, const float* __restrict__ sc,
               const float* __restrict__ sh, __half* __restrict__ out) {
    int row = blockIdx.x;
    const float* xr = x + (size_t)row * DD;
    float v[8];
    float s = 0.f, sq = 0.f;
#pragma unroll
    for (int i = 0; i < 8; i++) {
        v[i] = xr[threadIdx.x + i*256];
        s += v[i]; sq += v[i]*v[i];
    }
    __shared__ float rs[8], rq[8];
    __shared__ float s_mean, s_rstd;
#pragma unroll
    for (int o = 16; o > 0; o >>= 1) {
        s  += __shfl_down_sync(0xFFFFFFFFu, s,  o);
        sq += __shfl_down_sync(0xFFFFFFFFu, sq, o);
    }
    int w = threadIdx.x >> 5;
    if ((threadIdx.x & 31) == 0) { rs[w] = s; rq[w] = sq; }
    __syncthreads();
    if (threadIdx.x == 0) {
        float ts = 0.f, tq = 0.f;
#pragma unroll
        for (int i = 0; i < 8; i++) { ts += rs[i]; tq += rq[i]; }
        float mean = ts * (1.0f/DD);
        s_mean = mean;
        s_rstd = rsqrtf(tq * (1.0f/DD) - mean*mean + EPSV);
    }
    __syncthreads();
    float mean = s_mean, rstd = s_rstd;
    __half* orow = out + (size_t)row * DD;
#pragma unroll
    for (int i = 0; i < 8; i++) {
        int d = threadIdx.x + i*256;
        orow[d] = __float2half(sc[d]*(v[i]-mean)*rstd + sh[d]);
    }
}

// ---------------- FP16 GEMM: C = A[M,K] @ Wt[N,K]^T ----------------
#define KSTEP   64
#define ROWH    72
#define T_BYTES (128*ROWH*2)
#define STG_B   (2*T_BYTES)
#define G_SMEM  (3*STG_B)

// EPI 0: Ch=acc   EPI 1: Cf=acc+bias+R   EPI 2: Ch=gelu(acc+bias)
template<int EPI>
__global__ __launch_bounds__(256, 2)
void mma_gemm(const __half* __restrict__ A, const __half* __restrict__ Bt,
              const float* __restrict__ bias, const float* __restrict__ R,
              float* __restrict__ Cf, __half* __restrict__ Ch, int N, int K) {
    extern __shared__ char dsm[];
    const int tid = threadIdx.x;
    const int lane = tid & 31;
    const int wid = tid >> 5;
    const int warpM = wid & 1;
    const int warpN = wid >> 1;
    const int m0 = blockIdx.y * 128;
    const int n0 = blockIdx.x * 128;
    const uint32_t sb = smem_u32(dsm);

    float acc[4][4][4];
#pragma unroll
    for (int i = 0; i < 4; i++)
#pragma unroll
        for (int j = 0; j < 4; j++)
#pragma unroll
            for (int u = 0; u < 4; u++) acc[i][j][u] = 0.f;

    const int NT = K / KSTEP;

    auto load_stage = [&](int s, int kk) {
        uint32_t ab = sb + s*STG_B;
        uint32_t bb = ab + T_BYTES;
#pragma unroll
        for (int i = 0; i < 4; i++) {
            int idx = i*256 + tid;
            int r = idx >> 3, c = idx & 7;
            cp_async16(ab + (r*ROWH + c*8)*2, A  + (size_t)(m0 + r)*K + kk + c*8);
            cp_async16(bb + (r*ROWH + c*8)*2, Bt + (size_t)(n0 + r)*K + kk + c*8);
        }
    };

    load_stage(0, 0); cp_commit();
    load_stage(1, KSTEP); cp_commit();

    const int j  = lane >> 3;
    const int rr = lane & 7;
    const uint32_t offA = ((warpM*64 + ((j&1)<<3) + rr) * ROWH + (j>>1)*8) * 2;
    const uint32_t offB = ((warpN*32 + (j>>1)*8  + rr) * ROWH + (j&1)*8) * 2;

    for (int t = 0; t < NT; t++) {
        cp_wait1();
        __syncthreads();
        if (t + 2 < NT) { load_stage((t+2)%3, (t+2)*KSTEP); cp_commit(); }

        int s = t % 3;
        uint32_t abase = sb + s*STG_B + offA;
        uint32_t bbase = sb + s*STG_B + T_BYTES + offB;
#pragma unroll
        for (int k16 = 0; k16 < 4; k16++) {
            uint32_t ka = abase + k16*32;
            uint32_t kb = bbase + k16*32;
            uint32_t afr[4][4];
#pragma unroll
            for (int mt = 0; mt < 4; mt++)
                ldmx4(afr[mt], ka + mt*(16*ROWH*2));
            uint32_t bfr[4][2];
            ldmx4(&bfr[0][0], kb);
            ldmx4(&bfr[2][0], kb + 16*ROWH*2);
#pragma unroll
            for (int mt = 0; mt < 4; mt++)
#pragma unroll
                for (int nt = 0; nt < 4; nt++)
                    mma_f16(acc[mt][nt], afr[mt], bfr[nt]);
        }
    }

#pragma unroll
    for (int mt = 0; mt < 4; mt++) {
#pragma unroll
        for (int half_ = 0; half_ < 2; half_++) {
            int m = m0 + warpM*64 + mt*16 + (lane >> 2) + half_*8;
#pragma unroll
            for (int nt = 0; nt < 4; nt++) {
                int n = n0 + warpN*32 + nt*8 + 2*(lane & 3);
                float v0 = acc[mt][nt][half_*2 + 0];
                float v1 = acc[mt][nt][half_*2 + 1];
                if (EPI == 0) {
                    *(__half2*)(Ch + (size_t)m*N + n) = __floats2half2_rn(v0, v1);
                } else if (EPI == 1) {
                    const float2 bb = *(const float2*)(bias + n);
                    const float2 rv = *(const float2*)(R + (size_t)m*N + n);
                    float2 o; o.x = v0 + bb.x + rv.x; o.y = v1 + bb.y + rv.y;
                    *(float2*)(Cf + (size_t)m*N + n) = o;
                } else {
                    const float2 bb = *(const float2*)(bias + n);
                    *(__half2*)(Ch + (size_t)m*N + n) =
                        __floats2half2_rn(gelu_f(v0 + bb.x), gelu_f(v1 + bb.y));
                }
            }
        }
    }
}

// ---------------- causal flash attention (fp16, P-in-registers, cp.async KV ring) ----------------
#define KVROWH 136                         // 128 + 8 pad halfs (272B)
#define KV_TILE (64*KVROWH*2)              // 17408 B
#define KV_STG  (2*KV_TILE)                // K tile + V tile per stage
#define Q_BYTES (128*KVROWH*2)             // 34816 B
#define ATT_SMEM (Q_BYTES + 2*KV_STG)      // 104448 B

__global__ __launch_bounds__(256)
void attn_mma(const __half* __restrict__ Q, const __half* __restrict__ Kg,
              const __half* __restrict__ V, __half* __restrict__ O, int ld) {
    extern __shared__ __half hsm[];
    __half* Qs = hsm;
    const uint32_t sb = smem_u32(hsm);

    const int tid = threadIdx.x;
    const int lane = tid & 31;
    const int w = tid >> 5;
    const int r0 = lane >> 2;
    const int c0 = lane & 3;
    const int j  = lane >> 3;
    const int rr = lane & 7;
    const int q0 = blockIdx.x * 128;
    const int b = blockIdx.y >> 4;
    const int h = blockIdx.y & 15;
    const float rscale = 0.08838834764831845f;
    size_t ibase = ((size_t)b * SS) * ld + (size_t)h * HD;
    size_t obase = ((size_t)b * SS) * DD + (size_t)h * HD;

    // Q tile (plain vector loads; covered by first __syncthreads)
#pragma unroll
    for (int i = 0; i < 8; i++) {
        int idx = i*256 + tid;
        int r = idx >> 4, c = (idx & 15)*8;
        *(uint4*)(Qs + r*KVROWH + c) = *(const uint4*)(Q + ibase + (size_t)(q0 + r)*ld + c);
    }

    auto load_kv = [&](int kt) {
        int s = kt & 1;
        int k0 = kt * 64;
        uint32_t kb = sb + Q_BYTES + s*KV_STG;
        uint32_t vb = kb + KV_TILE;
#pragma unroll
        for (int i = 0; i < 4; i++) {
            int idx = i*256 + tid;
            int r = idx >> 4, c = (idx & 15)*8;
            cp_async16(kb + (r*KVROWH + c)*2, Kg + ibase + (size_t)(k0 + r)*ld + c);
            cp_async16(vb + (r*KVROWH + c)*2, V  + ibase + (size_t)(k0 + r)*ld + c);
        }
    };

    float acc[16][4];
#pragma unroll
    for (int i = 0; i < 16; i++)
#pragma unroll
        for (int u = 0; u < 4; u++) acc[i][u] = 0.f;
    float m0r = -1e30f, m1r = -1e30f, l0r = 0.f, l1r = 0.f;
    const int qi0 = q0 + w*16 + r0;
    const int qi1 = qi0 + 8;

    const uint32_t offQ = ((w*16 + ((j&1)<<3) + rr)*KVROWH + (j>>1)*8)*2;
    const uint32_t offK = (((j>>1)*8 + rr)*KVROWH + (j&1)*8)*2;
    const uint32_t offV = (((j&1)*8 + rr)*KVROWH + (j>>1)*8)*2;

    const int nkt = (q0 >> 6) + 2;
    load_kv(0); cp_commit();

    for (int kt = 0; kt < nkt; kt++) {
        int k0 = kt * 64;
        cp_wait0();
        __syncthreads();
        if (kt + 1 < nkt) { load_kv(kt + 1); cp_commit(); }

        int s = kt & 1;
        const uint32_t sK = sb + Q_BYTES + s*KV_STG;
        const uint32_t sV = sK + KV_TILE;

        // S = Q @ K^T
        float sc[8][4];
#pragma unroll
        for (int nt = 0; nt < 8; nt++)
#pragma unroll
            for (int u = 0; u < 4; u++) sc[nt][u] = 0.f;
#pragma unroll
        for (int kc = 0; kc < 8; kc++) {
            uint32_t a[4];
            ldmx4(a, sb + offQ + kc*32);
#pragma unroll
            for (int g = 0; g < 4; g++) {
                uint32_t bb[4];
                ldmx4(bb, sK + offK + kc*32 + g*(16*KVROWH*2));
                mma_f16(sc[2*g    ], a, bb);
                mma_f16(sc[2*g + 1], a, bb + 2);
            }
        }
        // scale + causal mask
#pragma unroll
        for (int nt = 0; nt < 8; nt++)
#pragma unroll
            for (int u = 0; u < 4; u++) sc[nt][u] *= rscale;
        if (k0 + 63 > qi0) {
#pragma unroll
            for (int nt = 0; nt < 8; nt++) {
                int cj = k0 + nt*8 + 2*c0;
                if (cj     > qi0) sc[nt][0] = -1e30f;
                if (cj + 1 > qi0) sc[nt][1] = -1e30f;
                if (cj     > qi1) sc[nt][2] = -1e30f;
                if (cj + 1 > qi1) sc[nt][3] = -1e30f;
            }
        }
        // online softmax (rows qi0, qi1); P stays in registers
        float tm0 = -1e30f, tm1 = -1e30f;
#pragma unroll
        for (int nt = 0; nt < 8; nt++) {
            tm0 = fmaxf(tm0, fmaxf(sc[nt][0], sc[nt][1]));
            tm1 = fmaxf(tm1, fmaxf(sc[nt][2], sc[nt][3]));
        }
        tm0 = fmaxf(tm0, __shfl_xor_sync(0xFFFFFFFFu, tm0, 1));
        tm0 = fmaxf(tm0, __shfl_xor_sync(0xFFFFFFFFu, tm0, 2));
        tm1 = fmaxf(tm1, __shfl_xor_sync(0xFFFFFFFFu, tm1, 1));
        tm1 = fmaxf(tm1, __shfl_xor_sync(0xFFFFFFFFu, tm1, 2));
        float mn0 = fmaxf(m0r, tm0), f0 = __expf(m0r - mn0);
        float mn1 = fmaxf(m1r, tm1), f1 = __expf(m1r - mn1);
        float ps0 = 0.f, ps1 = 0.f;
#pragma unroll
        for (int nt = 0; nt < 8; nt++) {
            sc[nt][0] = __expf(sc[nt][0] - mn0);
            sc[nt][1] = __expf(sc[nt][1] - mn0);
            sc[nt][2] = __expf(sc[nt][2] - mn1);
            sc[nt][3] = __expf(sc[nt][3] - mn1);
            ps0 += sc[nt][0] + sc[nt][1];
            ps1 += sc[nt][2] + sc[nt][3];
        }
        ps0 += __shfl_xor_sync(0xFFFFFFFFu, ps0, 1);
        ps0 += __shfl_xor_sync(0xFFFFFFFFu, ps0, 2);
        ps1 += __shfl_xor_sync(0xFFFFFFFFu, ps1, 1);
        ps1 += __shfl_xor_sync(0xFFFFFFFFu, ps1, 2);
        l0r = l0r*f0 + ps0; m0r = mn0;
        l1r = l1r*f1 + ps1; m1r = mn1;
#pragma unroll
        for (int nt = 0; nt < 16; nt++) {
            acc[nt][0] *= f0; acc[nt][1] *= f0;
            acc[nt][2] *= f1; acc[nt][3] *= f1;
        }
        // O += P @ V : A-fragments built in registers from S C-fragments
#pragma unroll
        for (int g = 0; g < 4; g++) {
            uint32_t a[4];
            a[0] = pack_h2(sc[2*g  ][0], sc[2*g  ][1]);
            a[1] = pack_h2(sc[2*g  ][2], sc[2*g  ][3]);
            a[2] = pack_h2(sc[2*g+1][0], sc[2*g+1][1]);
            a[3] = pack_h2(sc[2*g+1][2], sc[2*g+1][3]);
#pragma unroll
            for (int g2 = 0; g2 < 8; g2++) {
                uint32_t bb[4];
                ldmx4t(bb, sV + offV + g*(16*KVROWH*2) + g2*32);
                mma_f16(acc[2*g2    ], a, bb);
                mma_f16(acc[2*g2 + 1], a, bb + 2);
            }
        }
    }

    float inv0 = 1.0f / l0r, inv1 = 1.0f / l1r;
#pragma unroll
    for (int nt = 0; nt < 16; nt++) {
        int n = nt*8 + 2*c0;
        *(__half2*)(O + obase + (size_t)qi0*DD + n) = __floats2half2_rn(acc[nt][0]*inv0, acc[nt][1]*inv0);
        *(__half2*)(O + obase + (size_t)qi1*DD + n) = __floats2half2_rn(acc[nt][2]*inv1, acc[nt][3]*inv1);
    }
}

// ---------------- launch ----------------
extern "C" void kernel_launch(void* const* d_in, const int* in_sizes, int n_in,
                              void* d_out, int out_size) {
    const float* x    = (const float*)d_in[0];
    const float* Wq   = (const float*)d_in[1];
    const float* Wk   = (const float*)d_in[2];
    const float* Wv   = (const float*)d_in[3];
    const float* Wo   = (const float*)d_in[4];
    const float* bo   = (const float*)d_in[5];
    const float* ln1s = (const float*)d_in[6];
    const float* ln1b = (const float*)d_in[7];
    const float* ln2s = (const float*)d_in[8];
    const float* ln2b = (const float*)d_in[9];
    const float* W1   = (const float*)d_in[10];
    const float* b1   = (const float*)d_in[11];
    const float* W2   = (const float*)d_in[12];
    const float* b2   = (const float*)d_in[13];
    float* out = (float*)d_out;

    __half *xn, *qkv, *ctx, *ff, *wqkvT, *woT, *w1T, *w2T;
    float* h;
    cudaGetSymbolAddress((void**)&xn,    g_xn);
    cudaGetSymbolAddress((void**)&qkv,   g_qkv);
    cudaGetSymbolAddress((void**)&ctx,   g_ctx);
    cudaGetSymbolAddress((void**)&h,     g_h);
    cudaGetSymbolAddress((void**)&ff,    g_ff);
    cudaGetSymbolAddress((void**)&wqkvT, g_wqkvT);
    cudaGetSymbolAddress((void**)&woT,   g_woT);
    cudaGetSymbolAddress((void**)&w1T,   g_w1T);
    cudaGetSymbolAddress((void**)&w2T,   g_w2T);

    cudaFuncSetAttribute(attn_mma, cudaFuncAttributeMaxDynamicSharedMemorySize, ATT_SMEM);
    cudaFuncSetAttribute(mma_gemm<0>, cudaFuncAttributeMaxDynamicSharedMemorySize, G_SMEM);
    cudaFuncSetAttribute(mma_gemm<1>, cudaFuncAttributeMaxDynamicSharedMemorySize, G_SMEM);
    cudaFuncSetAttribute(mma_gemm<2>, cudaFuncAttributeMaxDynamicSharedMemorySize, G_SMEM);

    dim3 t32(32, 8);
    transpose_half<<<dim3(DD/32,  DD/32), t32>>>(Wq, wqkvT, DD, DD, 0,    DD);
    transpose_half<<<dim3(DD/32,  DD/32), t32>>>(Wk, wqkvT, DD, DD, 2048, DD);
    transpose_half<<<dim3(DD/32,  DD/32), t32>>>(Wv, wqkvT, DD, DD, 4096, DD);
    transpose_half<<<dim3(DD/32,  DD/32), t32>>>(Wo, woT, DD, DD, 0, DD);
    transpose_half<<<dim3(DFF/32, DD/32), t32>>>(W1, w1T, DD, DFF, 0, DD);
    transpose_half<<<dim3(DD/32, DFF/32), t32>>>(W2, w2T, DFF, DD, 0, DFF);

    ln_kernel<<<MROW, 256>>>(x, ln1s, ln1b, xn);
    mma_gemm<0><<<dim3(QS/128, MROW/128), 256, G_SMEM>>>(
        xn, wqkvT, nullptr, nullptr, nullptr, qkv, QS, DD);
    attn_mma<<<dim3(SS/128, BB*HH), 256, ATT_SMEM>>>(qkv, qkv + 2048, qkv + 4096, ctx, QS);
    mma_gemm<1><<<dim3(DD/128, MROW/128), 256, G_SMEM>>>(
        ctx, woT, bo, x, h, nullptr, DD, DD);
    ln_kernel<<<MROW, 256>>>(h, ln2s, ln2b, xn);
    mma_gemm<2><<<dim3(DFF/128, MROW/128), 256, G_SMEM>>>(
        xn, w1T, b1, nullptr, nullptr, ff, DFF, DD);
    mma_gemm<1><<<dim3(DD/128, MROW/128), 256, G_SMEM>>>(
        ff, w2T, b2, h, out, nullptr, DD, DFF);
}